// round 15
// baseline (speedup 1.0000x reference)
#include <cuda_runtime.h>
#include <cuda_fp16.h>
#include <cstdint>

// ---------------- constants ----------------
#define C     256
#define NB    64
#define HW    784
#define NPAD  900                 // 30*30 padded image
#define PADROWS (NB*NPAD)         // 57600
#define NTT   12544               // total 2x2 tiles = 64*14*14
#define VSTRIDE ((size_t)NTT*C)   // 3211264

// gemm tiling
#define GSTAGES 3
#define G_ABYTES 16384            // 128 rows x 64 fp16
#define G_BBYTES 16384
#define G_STG (G_ABYTES + G_BBYTES)        // 32 KB
#define G_SMEM (GSTAGES * G_STG)           // 96 KB -> 2 CTAs/SM

// fused input-transform smem
#define PR 40                                  // patch row stride in halves (80B)
#define PATCH_BYTES (NPAD*PR*2)                // 72000
#define F_SMEM (PATCH_BYTES + 32*33*4)         // + fp32 transpose stage = 76224

// ---------------- device scratch (only touched from device code!) ----------------
__device__ __half g_xh[PADROWS*C];   // padded NHWC input fp16 (halo stays 0)
__device__ __half g_o1[PADROWS*C];   // padded conv1 output fp16 (halo stays 0)
__device__ __half g_U1[16*C*C];      // transformed weights GgG^T
__device__ __half g_U2[16*C*C];
__device__ __half g_V[16*NTT*C];     // input transform (fp16)
__device__ __half g_Mh[16*NTT*C];    // gemm output (fp16)
__device__ float g_s1[C], g_b1[C], g_s2[C], g_b2[C];

// ---------------- ptx helpers ----------------
__device__ __forceinline__ uint32_t smem_u32(const void* p) {
    uint32_t a;
    asm("{ .reg .u64 t; cvta.to.shared.u64 t, %1; cvt.u32.u64 %0, t; }" : "=r"(a) : "l"(p));
    return a;
}
__device__ __forceinline__ void cp16(uint32_t dst, const void* src) {
    asm volatile("cp.async.cg.shared.global [%0], [%1], 16;\n" :: "r"(dst), "l"(src));
}
__device__ __forceinline__ void cp_commit() { asm volatile("cp.async.commit_group;\n" ::); }
__device__ __forceinline__ void cp_wait1()  { asm volatile("cp.async.wait_group 1;\n" ::: "memory"); }
__device__ __forceinline__ void ldmx4(uint32_t* r, uint32_t addr) {
    asm volatile("ldmatrix.sync.aligned.m8n8.x4.shared.b16 {%0,%1,%2,%3}, [%4];"
        : "=r"(r[0]), "=r"(r[1]), "=r"(r[2]), "=r"(r[3]) : "r"(addr));
}
__device__ __forceinline__ void mma16816_f(float* c, const uint32_t* a, const uint32_t* b) {
    asm volatile("mma.sync.aligned.m16n8k16.row.col.f32.f16.f16.f32 "
        "{%0,%1,%2,%3}, {%4,%5,%6,%7}, {%8,%9}, {%0,%1,%2,%3};"
        : "+f"(c[0]), "+f"(c[1]), "+f"(c[2]), "+f"(c[3])
        : "r"(a[0]), "r"(a[1]), "r"(a[2]), "r"(a[3]), "r"(b[0]), "r"(b[1]));
}
#define SW(off) ((off) ^ (((off) >> 3) & 0x70))

// ---------------- prep: BN consts + weight transform U = G g G^T ----------------
__global__ void prep(const float* __restrict__ w1, const float* __restrict__ w2,
                     const float* __restrict__ g1, const float* __restrict__ b1,
                     const float* __restrict__ m1, const float* __restrict__ v1,
                     const float* __restrict__ g2, const float* __restrict__ b2,
                     const float* __restrict__ m2, const float* __restrict__ v2) {
    int co = blockIdx.x, which = blockIdx.y, ci = threadIdx.x;
    if (co == 256) {
        if (which == 0) {
            float inv = g1[ci] * rsqrtf(v1[ci] + 1e-5f);
            g_s1[ci] = 0.02f * inv; g_b1[ci] = b1[ci] - m1[ci] * inv;
        } else {
            float inv = g2[ci] * rsqrtf(v2[ci] + 1e-5f);
            g_s2[ci] = 0.02f * inv; g_b2[ci] = b2[ci] - m2[ci] * inv;
        }
        return;
    }
    const float* w = which ? w2 : w1;
    __half* U = which ? g_U2 : g_U1;
    float g[3][3];
    #pragma unroll
    for (int r = 0; r < 3; r++)
        #pragma unroll
        for (int c = 0; c < 3; c++) {
            float v = w[((co * C + ci) * 3 + r) * 3 + c];
            g[r][c] = (v > 0.f) ? 1.f : ((v < 0.f) ? -1.f : 0.f);
        }
    float T[4][3];
    #pragma unroll
    for (int c = 0; c < 3; c++) {
        T[0][c] = g[0][c];
        T[1][c] = 0.5f * (g[0][c] + g[1][c] + g[2][c]);
        T[2][c] = 0.5f * (g[0][c] - g[1][c] + g[2][c]);
        T[3][c] = g[2][c];
    }
    #pragma unroll
    for (int i = 0; i < 4; i++) {
        float u0 = T[i][0];
        float u1 = 0.5f * (T[i][0] + T[i][1] + T[i][2]);
        float u2 = 0.5f * (T[i][0] - T[i][1] + T[i][2]);
        float u3 = T[i][2];
        int base = co * C + ci;
        U[(i * 4 + 0) * (C * C) + base] = __float2half_rn(u0);
        U[(i * 4 + 1) * (C * C) + base] = __float2half_rn(u1);
        U[(i * 4 + 2) * (C * C) + base] = __float2half_rn(u2);
        U[(i * 4 + 3) * (C * C) + base] = __float2half_rn(u3);
    }
}

// ---------------- fused: NCHW fp32 -> (g_xh fp16 NHWC, V) for conv1 ----------------
// grid (8 chgrp, 64 n), block 256. Patch held in smem; xpose kernel eliminated.
__global__ __launch_bounds__(256) void wino_in0f(const float* __restrict__ x) {
    extern __shared__ char sm[];
    __half* patch = (__half*)sm;                    // [900][PR]
    float* tst = (float*)(sm + PATCH_BYTES);        // [32][33]
    const int t = threadIdx.x;
    const int tx = t & 31, ty = t >> 5;             // (32, 8)
    const int chg = blockIdx.x;                     // 0..7 (32-ch group)
    const int n = blockIdx.y;

    // zero patch (halo must be 0)
    {
        const uint4 z = make_uint4(0, 0, 0, 0);
        #pragma unroll
        for (int i = 0; i < 18; i++) {
            int off = (t + i * 256) * 8;            // halves
            if (off < NPAD * PR) *(uint4*)(patch + off) = z;
        }
    }
    __syncthreads();

    const float* xb = x + ((size_t)n * C + chg * 32) * HW;
    __half* gxb = g_xh + (size_t)n * NPAD * C + chg * 32;

    // phase 1: 32x32 staged transpose, fp32 -> fp16, fill patch + g_xh
    for (int pt = 0; pt < 25; pt++) {
        #pragma unroll
        for (int i = 0; i < 4; i++) {
            int hw = pt * 32 + tx;
            int c = ty + i * 8;
            tst[c * 33 + tx] = (hw < HW) ? xb[(size_t)c * HW + hw] : 0.f;
        }
        __syncthreads();
        #pragma unroll
        for (int i = 0; i < 4; i++) {
            int hw2 = pt * 32 + ty + i * 8;
            if (hw2 < HW) {
                int h = hw2 / 28, w = hw2 - h * 28;
                __half v = __float2half_rn(tst[tx * 33 + ty + i * 8]);
                int ppx = (h + 1) * 30 + (w + 1);
                patch[ppx * PR + tx] = v;
                gxb[(size_t)ppx * C + tx] = v;
            }
        }
        __syncthreads();
    }

    // phase 2: V = B^T d B for 196 tiles x 32 ch (4 octets)
    const int lane = t & 31, wr = t >> 5;
    const int tileL = lane & 7;          // 8 tiles per warp -> distinct smem banks
    const int oct = (lane >> 3) & 3;     // 4 ch-octets
    for (int it = 0; it < 4; it++) {
        int tile = it * 64 + wr * 8 + tileL;
        if (tile >= 196) break;
        int ti = tile / 14, tj = tile - ti * 14;
        const __half* bp = patch + ((2 * ti) * 30 + 2 * tj) * PR + oct * 8;

        uint4 d16[16];
        #pragma unroll
        for (int i2 = 0; i2 < 4; i2++)
            #pragma unroll
            for (int j2 = 0; j2 < 4; j2++)
                d16[i2 * 4 + j2] = *(const uint4*)(bp + (i2 * 30 + j2) * PR);

        __half2 vout[16][4];
        #pragma unroll
        for (int k = 0; k < 8; k++) {
            float d[4][4];
            #pragma unroll
            for (int p = 0; p < 16; p++) {
                uint32_t wd = ((const uint32_t*)&d16[p])[k >> 1];
                float2 f = __half22float2(*(__half2*)&wd);
                d[p >> 2][p & 3] = (k & 1) ? f.y : f.x;
            }
            float tt[4][4];
            #pragma unroll
            for (int c = 0; c < 4; c++) {
                tt[0][c] = d[0][c] - d[2][c];
                tt[1][c] = d[1][c] + d[2][c];
                tt[2][c] = d[2][c] - d[1][c];
                tt[3][c] = d[1][c] - d[3][c];
            }
            #pragma unroll
            for (int i2 = 0; i2 < 4; i2++) {
                float v[4];
                v[0] = tt[i2][0] - tt[i2][2];
                v[1] = tt[i2][1] + tt[i2][2];
                v[2] = tt[i2][2] - tt[i2][1];
                v[3] = tt[i2][1] - tt[i2][3];
                #pragma unroll
                for (int j2 = 0; j2 < 4; j2++) {
                    __half hv = __float2half_rn(v[j2]);
                    int nu = i2 * 4 + j2, wdi = k >> 1;
                    if ((k & 1) == 0) vout[nu][wdi] = __halves2half2(hv, hv);
                    else vout[nu][wdi] = __halves2half2(__low2half(vout[nu][wdi]), hv);
                }
            }
        }
        size_t mo = (size_t)(n * 196 + tile) * C + chg * 32 + oct * 8;
        #pragma unroll
        for (int nu = 0; nu < 16; nu++)
            *(uint4*)(g_V + nu * VSTRIDE + mo) = *(uint4*)vout[nu];
    }
}

// ---------------- input transform for conv2: V = B^T d B from g_o1 ----------------
// block 256 = 8 tile-slots x 32 ci-octets; grid 1568
__global__ __launch_bounds__(256) void wino_in1() {
    const __half* src = g_o1;
    int t = threadIdx.x;
    int cig = t & 31, slot = t >> 5;
    int mp = blockIdx.x * 8 + slot;
    int n = mp / 196; int r0 = mp - n * 196;
    int ti = r0 / 14, tj = r0 - ti * 14;
    const __half* base = src + ((size_t)(n * NPAD + 2 * ti * 30 + 2 * tj)) * C + cig * 8;

    uint4 d16[16];
    #pragma unroll
    for (int i = 0; i < 4; i++)
        #pragma unroll
        for (int j = 0; j < 4; j++)
            d16[i * 4 + j] = *(const uint4*)(base + (size_t)(i * 30 + j) * C);

    __half2 vout[16][4];
    #pragma unroll
    for (int k = 0; k < 8; k++) {
        float d[4][4];
        #pragma unroll
        for (int p = 0; p < 16; p++) {
            uint32_t wd = ((const uint32_t*)&d16[p])[k >> 1];
            float2 f = __half22float2(*(__half2*)&wd);
            d[p >> 2][p & 3] = (k & 1) ? f.y : f.x;
        }
        float tt[4][4];
        #pragma unroll
        for (int c = 0; c < 4; c++) {
            tt[0][c] = d[0][c] - d[2][c];
            tt[1][c] = d[1][c] + d[2][c];
            tt[2][c] = d[2][c] - d[1][c];
            tt[3][c] = d[1][c] - d[3][c];
        }
        #pragma unroll
        for (int i = 0; i < 4; i++) {
            float v[4];
            v[0] = tt[i][0] - tt[i][2];
            v[1] = tt[i][1] + tt[i][2];
            v[2] = tt[i][2] - tt[i][1];
            v[3] = tt[i][1] - tt[i][3];
            #pragma unroll
            for (int j = 0; j < 4; j++) {
                __half hv = __float2half_rn(v[j]);
                int nu = i * 4 + j, wdi = k >> 1;
                if ((k & 1) == 0) vout[nu][wdi] = __halves2half2(hv, hv);
                else vout[nu][wdi] = __halves2half2(__low2half(vout[nu][wdi]), hv);
            }
        }
    }
    size_t mo = (size_t)mp * C + cig * 8;
    #pragma unroll
    for (int nu = 0; nu < 16; nu++)
        *(uint4*)(g_V + nu * VSTRIDE + mo) = *(uint4*)vout[nu];
}

// ---------------- batched GEMM: M[nu] = V[nu] * U[nu]^T ----------------
// grid (2, 98, 16), block 256 (8 warps 2x4, warp tile 64x32), 3-stage 96KB, occ 2.
// f32 accumulation (legacy-HMMA chip floor); A fragments double-buffered across ks.
template <int WHICH>
__global__ __launch_bounds__(256, 2) void gemm_wino() {
    extern __shared__ char smem[];
    const uint32_t sb = smem_u32(smem);
    const int bn_ = blockIdx.x, bm = blockIdx.y, nu = blockIdx.z;
    const __half* Vb = g_V + (size_t)nu * VSTRIDE;
    const __half* Ub = (WHICH ? g_U2 : g_U1) + (size_t)nu * (C * C);

    const int tid = threadIdx.x;
    const int wid = tid >> 5, lane = tid & 31;
    const int row = tid >> 1, hf = tid & 1;
    const __half* Arow = Vb + (size_t)(bm * 128 + row) * C + hf * 32;
    const __half* Brow = Ub + (size_t)(bn_ * 128 + row) * C + hf * 32;

    auto loadChunk = [&](int k) {
        const uint32_t base = sb + (k % GSTAGES) * G_STG;
        const uint32_t ro = (uint32_t)row * 128 + hf * 64;
        #pragma unroll
        for (int i = 0; i < 4; i++) {
            uint32_t o = ro + i * 16;
            cp16(base + SW(o), Arow + k * 64 + i * 8);
            cp16(base + G_ABYTES + SW(o), Brow + k * 64 + i * 8);
        }
        cp_commit();
    };

    const int wm = wid & 1, wn = wid >> 1;
    const int lq = lane >> 3, l7 = lane & 7;
    const int aro = (lq & 1) * 8 + l7, aqh = lq >> 1;
    const int bro = (lq >> 1) * 8 + l7, bqh = lq & 1;

    float acc[4][4][4];
    #pragma unroll
    for (int i = 0; i < 4; i++)
        #pragma unroll
        for (int j = 0; j < 4; j++)
            #pragma unroll
            for (int k = 0; k < 4; k++) acc[i][j][k] = 0.f;

    uint32_t af[2][4][4];

    loadChunk(0);
    loadChunk(1);

    #pragma unroll
    for (int k = 0; k < 4; k++) {
        cp_wait1();
        __syncthreads();
        if (k + 2 < 4) loadChunk(k + 2); else cp_commit();

        const uint32_t aB = sb + (k % GSTAGES) * G_STG + (uint32_t)(wm * 64) * 128;
        const uint32_t bB = sb + (k % GSTAGES) * G_STG + G_ABYTES + (uint32_t)(wn * 32) * 128;

        #pragma unroll
        for (int mt = 0; mt < 4; mt++) {
            int rw = mt * 16 + aro;
            ldmx4(af[0][mt], aB + (uint32_t)rw * 128 + (uint32_t)((aqh ^ (rw & 7)) * 16));
        }

        #pragma unroll
        for (int ks = 0; ks < 4; ks++) {
            const int cur = ks & 1, nxt = cur ^ 1;
            if (ks < 3) {
                #pragma unroll
                for (int mt = 0; mt < 4; mt++) {
                    int rw = mt * 16 + aro;
                    ldmx4(af[nxt][mt],
                          aB + (uint32_t)rw * 128 + (uint32_t)((((ks + 1) * 2 + aqh) ^ (rw & 7)) * 16));
                }
            }
            uint32_t bf[2][4];
            #pragma unroll
            for (int nt2 = 0; nt2 < 2; nt2++) {
                int rw = nt2 * 16 + bro;
                uint32_t cx = (uint32_t)(((ks * 2 + bqh) ^ (rw & 7)) * 16);
                ldmx4(bf[nt2], bB + (uint32_t)rw * 128 + cx);
            }
            #pragma unroll
            for (int mt = 0; mt < 4; mt++)
                #pragma unroll
                for (int nt = 0; nt < 4; nt++)
                    mma16816_f(acc[mt][nt], af[cur][mt], &bf[nt >> 1][(nt & 1) * 2]);
        }
    }

    // epilogue: fp16 M
    const int lr = lane >> 2, lc = (lane & 3) * 2;
    __half* Mb = g_Mh + (size_t)nu * VSTRIDE;
    #pragma unroll
    for (int nt = 0; nt < 4; nt++) {
        const int co = bn_ * 128 + wn * 32 + nt * 8 + lc;
        #pragma unroll
        for (int mt = 0; mt < 4; mt++) {
            const int m0 = bm * 128 + wm * 64 + mt * 16 + lr;
            *(__half2*)(Mb + (size_t)m0 * C + co) = __floats2half2_rn(acc[mt][nt][0], acc[mt][nt][1]);
            *(__half2*)(Mb + (size_t)(m0 + 8) * C + co) = __floats2half2_rn(acc[mt][nt][2], acc[mt][nt][3]);
        }
    }
}

// ---------------- output transform: Y = A^T M A, + BN (+res) + ReLU ----------------
// block 256 = 4 tile-slots x 64 co-quads; grid 3136
// MODE 1: residual comes from g_xh (fp16 NHWC padded)
template <int MODE>
__global__ __launch_bounds__(256) void wino_out(float* __restrict__ out) {
    __shared__ float st[16 * 257];   // MODE1 transpose buffer
    int t = threadIdx.x;
    int cog = t & 63, slot = t >> 6;
    int mp = blockIdx.x * 4 + slot;
    int n = mp / 196; int r0 = mp - n * 196;
    int ti = r0 / 14, tj = r0 - ti * 14;
    const float* scp = MODE ? g_s2 : g_s1;
    const float* bip = MODE ? g_b2 : g_b1;

    size_t mo = (size_t)mp * C + cog * 4;
    uint2 m16[16];
    #pragma unroll
    for (int nu = 0; nu < 16; nu++)
        m16[nu] = *(const uint2*)(g_Mh + nu * VSTRIDE + mo);

    uint2 rx[4];
    if (MODE == 1) {
        const __half* xh = g_xh + ((size_t)(n * NPAD + (2 * ti + 1) * 30 + 2 * tj + 1)) * C + cog * 4;
        rx[0] = *(const uint2*)(xh);
        rx[1] = *(const uint2*)(xh + C);
        rx[2] = *(const uint2*)(xh + 30 * C);
        rx[3] = *(const uint2*)(xh + 31 * C);
    }

    __half2 oreg[4][2];
    #pragma unroll
    for (int k = 0; k < 4; k++) {
        float Mv[16];
        #pragma unroll
        for (int p = 0; p < 16; p++) {
            uint32_t wd = ((const uint32_t*)&m16[p])[k >> 1];
            float2 f = __half22float2(*(__half2*)&wd);
            Mv[p] = (k & 1) ? f.y : f.x;
        }
        float t0[4], t1[4];
        #pragma unroll
        for (int c = 0; c < 4; c++) {
            t0[c] = Mv[c] + Mv[4 + c] + Mv[8 + c];
            t1[c] = Mv[4 + c] - Mv[8 + c] - Mv[12 + c];
        }
        float y[4];
        y[0] = t0[0] + t0[1] + t0[2];
        y[1] = t0[1] - t0[2] - t0[3];
        y[2] = t1[0] + t1[1] + t1[2];
        y[3] = t1[1] - t1[2] - t1[3];
        const int co = cog * 4 + k;
        const float s = scp[co], bb = bip[co];
        #pragma unroll
        for (int p = 0; p < 4; p++) y[p] = y[p] * s + bb;

        if (MODE == 0) {
            #pragma unroll
            for (int p = 0; p < 4; p++) {
                __half hv = __float2half_rn(fmaxf(y[p], 0.f));
                int wdi = k >> 1;
                if ((k & 1) == 0) oreg[p][wdi] = __halves2half2(hv, hv);
                else oreg[p][wdi] = __halves2half2(__low2half(oreg[p][wdi]), hv);
            }
        } else {
            #pragma unroll
            for (int p = 0; p < 4; p++) {
                float r = __half2float(((const __half*)&rx[p])[k]);
                st[(slot * 4 + p) * 257 + co] = y[p] + r;
            }
        }
    }

    if (MODE == 0) {
        __half* dst = g_o1 + ((size_t)(n * NPAD + (2 * ti + 1) * 30 + 2 * tj + 1)) * C + cog * 4;
        *(uint2*)(dst)          = *(uint2*)oreg[0];
        *(uint2*)(dst + C)      = *(uint2*)oreg[1];
        *(uint2*)(dst + 30 * C) = *(uint2*)oreg[2];
        *(uint2*)(dst + 31 * C) = *(uint2*)oreg[3];
    } else {
        __syncthreads();
        const int l = t & 7, q = t >> 3;
        const int s2 = l >> 1, c2 = l & 1;
        const int r2 = q & 1, coq = q >> 1;          // coq 0..15
        const int mp2 = blockIdx.x * 4 + s2;
        const int n2 = mp2 / 196; int rr2 = mp2 - n2 * 196;
        const int ti2 = rr2 / 14, tj2 = rr2 - ti2 * 14;
        const int h = 2 * ti2 + r2, w = 2 * tj2 + c2;
        const int srow = (s2 * 4 + r2 * 2 + c2) * 257;
        #pragma unroll
        for (int cc = 0; cc < 16; cc++) {
            const int co2 = coq * 16 + cc;
            const size_t gi = ((size_t)n2 * C + co2) * HW + h * 28 + w;
            out[gi] = fmaxf(st[srow + co2], 0.f);
        }
    }
}

// ---------------- launch ----------------
extern "C" void kernel_launch(void* const* d_in, const int* in_sizes, int n_in,
                              void* d_out, int out_size) {
    (void)in_sizes; (void)n_in; (void)out_size;
    const float* x  = (const float*)d_in[0];
    const float* w1 = (const float*)d_in[1];
    const float* g1 = (const float*)d_in[2];
    const float* b1 = (const float*)d_in[3];
    const float* m1 = (const float*)d_in[4];
    const float* v1 = (const float*)d_in[5];
    const float* w2 = (const float*)d_in[6];
    const float* g2 = (const float*)d_in[7];
    const float* b2 = (const float*)d_in[8];
    const float* m2 = (const float*)d_in[9];
    const float* v2 = (const float*)d_in[10];
    float* out = (float*)d_out;

    cudaFuncSetAttribute(gemm_wino<0>, cudaFuncAttributeMaxDynamicSharedMemorySize, G_SMEM);
    cudaFuncSetAttribute(gemm_wino<1>, cudaFuncAttributeMaxDynamicSharedMemorySize, G_SMEM);
    cudaFuncSetAttribute(wino_in0f, cudaFuncAttributeMaxDynamicSharedMemorySize, F_SMEM);

    prep<<<dim3(257, 2), 256>>>(w1, w2, g1, b1, m1, v1, g2, b2, m2, v2);

    // conv1 (fused xpose + input transform)
    wino_in0f<<<dim3(8, 64), 256, F_SMEM>>>(x);
    gemm_wino<0><<<dim3(2, 98, 16), 256, G_SMEM>>>();
    wino_out<0><<<3136, 256>>>(nullptr);

    // conv2
    wino_in1<<<1568, 256>>>();
    gemm_wino<1><<<dim3(2, 98, 16), 256, G_SMEM>>>();
    wino_out<1><<<3136, 256>>>(out);
}

// round 16
// speedup vs baseline: 1.1060x; 1.1060x over previous
#include <cuda_runtime.h>
#include <cuda_fp16.h>
#include <cstdint>

// ---------------- constants ----------------
#define C     256
#define NB    64
#define HW    784
#define NPAD  900                 // 30*30 padded image
#define PADROWS (NB*NPAD)         // 57600
#define NTT   12544               // total 2x2 tiles = 64*14*14
#define VSTRIDE ((size_t)NTT*C)   // 3211264

// gemm tiling
#define GSTAGES 3
#define G_ABYTES 16384            // 128 rows x 64 fp16
#define G_BBYTES 16384
#define G_STG (G_ABYTES + G_BBYTES)        // 32 KB
#define G_SMEM (GSTAGES * G_STG)           // 96 KB -> 2 CTAs/SM

// ---------------- device scratch (only touched from device code!) ----------------
__device__ __half g_xh[PADROWS*C];   // padded NHWC input fp16 (halo stays 0)
__device__ __half g_o1[PADROWS*C];   // padded conv1 output fp16 (halo stays 0)
__device__ __half g_U1[16*C*C];      // transformed weights GgG^T
__device__ __half g_U2[16*C*C];
__device__ __half g_V[16*NTT*C];     // input transform (fp16)
__device__ __half g_Mh[16*NTT*C];    // gemm output (fp16)
__device__ float g_s1[C], g_b1[C], g_s2[C], g_b2[C];

// ---------------- ptx helpers ----------------
__device__ __forceinline__ uint32_t smem_u32(const void* p) {
    uint32_t a;
    asm("{ .reg .u64 t; cvta.to.shared.u64 t, %1; cvt.u32.u64 %0, t; }" : "=r"(a) : "l"(p));
    return a;
}
__device__ __forceinline__ void cp16(uint32_t dst, const void* src) {
    asm volatile("cp.async.cg.shared.global [%0], [%1], 16;\n" :: "r"(dst), "l"(src));
}
__device__ __forceinline__ void cp_commit() { asm volatile("cp.async.commit_group;\n" ::); }
__device__ __forceinline__ void cp_wait1()  { asm volatile("cp.async.wait_group 1;\n" ::: "memory"); }
__device__ __forceinline__ void ldmx4(uint32_t* r, uint32_t addr) {
    asm volatile("ldmatrix.sync.aligned.m8n8.x4.shared.b16 {%0,%1,%2,%3}, [%4];"
        : "=r"(r[0]), "=r"(r[1]), "=r"(r[2]), "=r"(r[3]) : "r"(addr));
}
__device__ __forceinline__ void mma16816_f(float* c, const uint32_t* a, const uint32_t* b) {
    asm volatile("mma.sync.aligned.m16n8k16.row.col.f32.f16.f16.f32 "
        "{%0,%1,%2,%3}, {%4,%5,%6,%7}, {%8,%9}, {%0,%1,%2,%3};"
        : "+f"(c[0]), "+f"(c[1]), "+f"(c[2]), "+f"(c[3])
        : "r"(a[0]), "r"(a[1]), "r"(a[2]), "r"(a[3]), "r"(b[0]), "r"(b[1]));
}
#define SW(off) ((off) ^ (((off) >> 3) & 0x70))

// ---------------- prep: BN consts + weight transform U = G g G^T ----------------
__global__ void prep(const float* __restrict__ w1, const float* __restrict__ w2,
                     const float* __restrict__ g1, const float* __restrict__ b1,
                     const float* __restrict__ m1, const float* __restrict__ v1,
                     const float* __restrict__ g2, const float* __restrict__ b2,
                     const float* __restrict__ m2, const float* __restrict__ v2) {
    int co = blockIdx.x, which = blockIdx.y, ci = threadIdx.x;
    if (co == 256) {
        if (which == 0) {
            float inv = g1[ci] * rsqrtf(v1[ci] + 1e-5f);
            g_s1[ci] = 0.02f * inv; g_b1[ci] = b1[ci] - m1[ci] * inv;
        } else {
            float inv = g2[ci] * rsqrtf(v2[ci] + 1e-5f);
            g_s2[ci] = 0.02f * inv; g_b2[ci] = b2[ci] - m2[ci] * inv;
        }
        return;
    }
    const float* w = which ? w2 : w1;
    __half* U = which ? g_U2 : g_U1;
    float g[3][3];
    #pragma unroll
    for (int r = 0; r < 3; r++)
        #pragma unroll
        for (int c = 0; c < 3; c++) {
            float v = w[((co * C + ci) * 3 + r) * 3 + c];
            g[r][c] = (v > 0.f) ? 1.f : ((v < 0.f) ? -1.f : 0.f);
        }
    float T[4][3];
    #pragma unroll
    for (int c = 0; c < 3; c++) {
        T[0][c] = g[0][c];
        T[1][c] = 0.5f * (g[0][c] + g[1][c] + g[2][c]);
        T[2][c] = 0.5f * (g[0][c] - g[1][c] + g[2][c]);
        T[3][c] = g[2][c];
    }
    #pragma unroll
    for (int i = 0; i < 4; i++) {
        float u0 = T[i][0];
        float u1 = 0.5f * (T[i][0] + T[i][1] + T[i][2]);
        float u2 = 0.5f * (T[i][0] - T[i][1] + T[i][2]);
        float u3 = T[i][2];
        int base = co * C + ci;
        U[(i * 4 + 0) * (C * C) + base] = __float2half_rn(u0);
        U[(i * 4 + 1) * (C * C) + base] = __float2half_rn(u1);
        U[(i * 4 + 2) * (C * C) + base] = __float2half_rn(u2);
        U[(i * 4 + 3) * (C * C) + base] = __float2half_rn(u3);
    }
}

// ---------------- NCHW -> padded NHWC fp16 ----------------
__global__ void xpose(const float* __restrict__ x) {
    __shared__ float t[32][33];
    int n = blockIdx.z, hwt = blockIdx.x, ct = blockIdx.y;
    int tx = threadIdx.x, ty = threadIdx.y;
    int hw = hwt * 32 + tx;
    #pragma unroll
    for (int i = 0; i < 4; i++) {
        int c = ct * 32 + ty + i * 8;
        t[ty + i * 8][tx] = (hw < HW) ? x[((size_t)n * C + c) * HW + hw] : 0.f;
    }
    __syncthreads();
    #pragma unroll
    for (int i = 0; i < 4; i++) {
        int hw2 = hwt * 32 + ty + i * 8;
        int c = ct * 32 + tx;
        if (hw2 < HW) {
            int h = hw2 / 28, w = hw2 - h * 28;
            g_xh[((size_t)(n * NPAD + (h + 1) * 30 + w + 1)) * C + c] =
                __float2half_rn(t[tx][ty + i * 8]);
        }
    }
}

// ---------------- input transform: V = B^T d B ----------------
// block 256 = 8 tile-slots x 32 ci-octets; grid 1568
template <int WHICH>
__global__ __launch_bounds__(256) void wino_in() {
    const __half* src = WHICH ? g_o1 : g_xh;
    int t = threadIdx.x;
    int cig = t & 31, slot = t >> 5;
    int mp = blockIdx.x * 8 + slot;
    int n = mp / 196; int r0 = mp - n * 196;
    int ti = r0 / 14, tj = r0 - ti * 14;
    const __half* base = src + ((size_t)(n * NPAD + 2 * ti * 30 + 2 * tj)) * C + cig * 8;

    uint4 d16[16];
    #pragma unroll
    for (int i = 0; i < 4; i++)
        #pragma unroll
        for (int j = 0; j < 4; j++)
            d16[i * 4 + j] = *(const uint4*)(base + (size_t)(i * 30 + j) * C);

    __half2 vout[16][4];
    #pragma unroll
    for (int k = 0; k < 8; k++) {
        float d[4][4];
        #pragma unroll
        for (int p = 0; p < 16; p++) {
            uint32_t wd = ((const uint32_t*)&d16[p])[k >> 1];
            float2 f = __half22float2(*(__half2*)&wd);
            d[p >> 2][p & 3] = (k & 1) ? f.y : f.x;
        }
        float tt[4][4];
        #pragma unroll
        for (int c = 0; c < 4; c++) {
            tt[0][c] = d[0][c] - d[2][c];
            tt[1][c] = d[1][c] + d[2][c];
            tt[2][c] = d[2][c] - d[1][c];
            tt[3][c] = d[1][c] - d[3][c];
        }
        #pragma unroll
        for (int i = 0; i < 4; i++) {
            float v[4];
            v[0] = tt[i][0] - tt[i][2];
            v[1] = tt[i][1] + tt[i][2];
            v[2] = tt[i][2] - tt[i][1];
            v[3] = tt[i][1] - tt[i][3];
            #pragma unroll
            for (int j = 0; j < 4; j++) {
                __half hv = __float2half_rn(v[j]);
                int nu = i * 4 + j, wdi = k >> 1;
                if ((k & 1) == 0) vout[nu][wdi] = __halves2half2(hv, hv);
                else vout[nu][wdi] = __halves2half2(__low2half(vout[nu][wdi]), hv);
            }
        }
    }
    size_t mo = (size_t)mp * C + cig * 8;
    #pragma unroll
    for (int nu = 0; nu < 16; nu++)
        *(uint4*)(g_V + nu * VSTRIDE + mo) = *(uint4*)vout[nu];
}

// ---------------- batched GEMM: M[nu] = V[nu] * U[nu]^T ----------------
// grid (2, 98, 16), block 256 (8 warps 2x4, warp tile 64x32), 3-stage 96KB, occ 2.
// f32 accumulation (legacy-HMMA chip floor); A fragments double-buffered across ks.
template <int WHICH>
__global__ __launch_bounds__(256, 2) void gemm_wino() {
    extern __shared__ char smem[];
    const uint32_t sb = smem_u32(smem);
    const int bn_ = blockIdx.x, bm = blockIdx.y, nu = blockIdx.z;
    const __half* Vb = g_V + (size_t)nu * VSTRIDE;
    const __half* Ub = (WHICH ? g_U2 : g_U1) + (size_t)nu * (C * C);

    const int tid = threadIdx.x;
    const int wid = tid >> 5, lane = tid & 31;
    const int row = tid >> 1, hf = tid & 1;
    const __half* Arow = Vb + (size_t)(bm * 128 + row) * C + hf * 32;
    const __half* Brow = Ub + (size_t)(bn_ * 128 + row) * C + hf * 32;

    auto loadChunk = [&](int k) {
        const uint32_t base = sb + (k % GSTAGES) * G_STG;
        const uint32_t ro = (uint32_t)row * 128 + hf * 64;
        #pragma unroll
        for (int i = 0; i < 4; i++) {
            uint32_t o = ro + i * 16;
            cp16(base + SW(o), Arow + k * 64 + i * 8);
            cp16(base + G_ABYTES + SW(o), Brow + k * 64 + i * 8);
        }
        cp_commit();
    };

    const int wm = wid & 1, wn = wid >> 1;
    const int lq = lane >> 3, l7 = lane & 7;
    const int aro = (lq & 1) * 8 + l7, aqh = lq >> 1;
    const int bro = (lq >> 1) * 8 + l7, bqh = lq & 1;

    float acc[4][4][4];
    #pragma unroll
    for (int i = 0; i < 4; i++)
        #pragma unroll
        for (int j = 0; j < 4; j++)
            #pragma unroll
            for (int k = 0; k < 4; k++) acc[i][j][k] = 0.f;

    uint32_t af[2][4][4];

    loadChunk(0);
    loadChunk(1);

    #pragma unroll
    for (int k = 0; k < 4; k++) {
        cp_wait1();
        __syncthreads();
        if (k + 2 < 4) loadChunk(k + 2); else cp_commit();

        const uint32_t aB = sb + (k % GSTAGES) * G_STG + (uint32_t)(wm * 64) * 128;
        const uint32_t bB = sb + (k % GSTAGES) * G_STG + G_ABYTES + (uint32_t)(wn * 32) * 128;

        #pragma unroll
        for (int mt = 0; mt < 4; mt++) {
            int rw = mt * 16 + aro;
            ldmx4(af[0][mt], aB + (uint32_t)rw * 128 + (uint32_t)((aqh ^ (rw & 7)) * 16));
        }

        #pragma unroll
        for (int ks = 0; ks < 4; ks++) {
            const int cur = ks & 1, nxt = cur ^ 1;
            if (ks < 3) {
                #pragma unroll
                for (int mt = 0; mt < 4; mt++) {
                    int rw = mt * 16 + aro;
                    ldmx4(af[nxt][mt],
                          aB + (uint32_t)rw * 128 + (uint32_t)((((ks + 1) * 2 + aqh) ^ (rw & 7)) * 16));
                }
            }
            uint32_t bf[2][4];
            #pragma unroll
            for (int nt2 = 0; nt2 < 2; nt2++) {
                int rw = nt2 * 16 + bro;
                uint32_t cx = (uint32_t)(((ks * 2 + bqh) ^ (rw & 7)) * 16);
                ldmx4(bf[nt2], bB + (uint32_t)rw * 128 + cx);
            }
            #pragma unroll
            for (int mt = 0; mt < 4; mt++)
                #pragma unroll
                for (int nt = 0; nt < 4; nt++)
                    mma16816_f(acc[mt][nt], af[cur][mt], &bf[nt >> 1][(nt & 1) * 2]);
        }
    }

    // epilogue: fp16 M
    const int lr = lane >> 2, lc = (lane & 3) * 2;
    __half* Mb = g_Mh + (size_t)nu * VSTRIDE;
    #pragma unroll
    for (int nt = 0; nt < 4; nt++) {
        const int co = bn_ * 128 + wn * 32 + nt * 8 + lc;
        #pragma unroll
        for (int mt = 0; mt < 4; mt++) {
            const int m0 = bm * 128 + wm * 64 + mt * 16 + lr;
            *(__half2*)(Mb + (size_t)m0 * C + co) = __floats2half2_rn(acc[mt][nt][0], acc[mt][nt][1]);
            *(__half2*)(Mb + (size_t)(m0 + 8) * C + co) = __floats2half2_rn(acc[mt][nt][2], acc[mt][nt][3]);
        }
    }
}

// ---------------- output transform: Y = A^T M A, + BN (+res) + ReLU ----------------
// block 256 = 4 tile-slots x 64 co-quads; grid 3136
// MODE 1: residual comes from g_xh (fp16 NHWC padded)
template <int MODE>
__global__ __launch_bounds__(256) void wino_out(float* __restrict__ out) {
    __shared__ float st[16 * 257];   // MODE1 transpose buffer
    int t = threadIdx.x;
    int cog = t & 63, slot = t >> 6;
    int mp = blockIdx.x * 4 + slot;
    int n = mp / 196; int r0 = mp - n * 196;
    int ti = r0 / 14, tj = r0 - ti * 14;
    const float* scp = MODE ? g_s2 : g_s1;
    const float* bip = MODE ? g_b2 : g_b1;

    size_t mo = (size_t)mp * C + cog * 4;
    uint2 m16[16];
    #pragma unroll
    for (int nu = 0; nu < 16; nu++)
        m16[nu] = *(const uint2*)(g_Mh + nu * VSTRIDE + mo);

    uint2 rx[4];
    if (MODE == 1) {
        const __half* xh = g_xh + ((size_t)(n * NPAD + (2 * ti + 1) * 30 + 2 * tj + 1)) * C + cog * 4;
        rx[0] = *(const uint2*)(xh);
        rx[1] = *(const uint2*)(xh + C);
        rx[2] = *(const uint2*)(xh + 30 * C);
        rx[3] = *(const uint2*)(xh + 31 * C);
    }

    __half2 oreg[4][2];
    #pragma unroll
    for (int k = 0; k < 4; k++) {
        float Mv[16];
        #pragma unroll
        for (int p = 0; p < 16; p++) {
            uint32_t wd = ((const uint32_t*)&m16[p])[k >> 1];
            float2 f = __half22float2(*(__half2*)&wd);
            Mv[p] = (k & 1) ? f.y : f.x;
        }
        float t0[4], t1[4];
        #pragma unroll
        for (int c = 0; c < 4; c++) {
            t0[c] = Mv[c] + Mv[4 + c] + Mv[8 + c];
            t1[c] = Mv[4 + c] - Mv[8 + c] - Mv[12 + c];
        }
        float y[4];
        y[0] = t0[0] + t0[1] + t0[2];
        y[1] = t0[1] - t0[2] - t0[3];
        y[2] = t1[0] + t1[1] + t1[2];
        y[3] = t1[1] - t1[2] - t1[3];
        const int co = cog * 4 + k;
        const float s = scp[co], bb = bip[co];
        #pragma unroll
        for (int p = 0; p < 4; p++) y[p] = y[p] * s + bb;

        if (MODE == 0) {
            #pragma unroll
            for (int p = 0; p < 4; p++) {
                __half hv = __float2half_rn(fmaxf(y[p], 0.f));
                int wdi = k >> 1;
                if ((k & 1) == 0) oreg[p][wdi] = __halves2half2(hv, hv);
                else oreg[p][wdi] = __halves2half2(__low2half(oreg[p][wdi]), hv);
            }
        } else {
            #pragma unroll
            for (int p = 0; p < 4; p++) {
                float r = __half2float(((const __half*)&rx[p])[k]);
                st[(slot * 4 + p) * 257 + co] = y[p] + r;
            }
        }
    }

    if (MODE == 0) {
        __half* dst = g_o1 + ((size_t)(n * NPAD + (2 * ti + 1) * 30 + 2 * tj + 1)) * C + cog * 4;
        *(uint2*)(dst)          = *(uint2*)oreg[0];
        *(uint2*)(dst + C)      = *(uint2*)oreg[1];
        *(uint2*)(dst + 30 * C) = *(uint2*)oreg[2];
        *(uint2*)(dst + 31 * C) = *(uint2*)oreg[3];
    } else {
        __syncthreads();
        const int l = t & 7, q = t >> 3;
        const int s2 = l >> 1, c2 = l & 1;
        const int r2 = q & 1, coq = q >> 1;          // coq 0..15
        const int mp2 = blockIdx.x * 4 + s2;
        const int n2 = mp2 / 196; int rr2 = mp2 - n2 * 196;
        const int ti2 = rr2 / 14, tj2 = rr2 - ti2 * 14;
        const int h = 2 * ti2 + r2, w = 2 * tj2 + c2;
        const int srow = (s2 * 4 + r2 * 2 + c2) * 257;
        #pragma unroll
        for (int cc = 0; cc < 16; cc++) {
            const int co2 = coq * 16 + cc;
            const size_t gi = ((size_t)n2 * C + co2) * HW + h * 28 + w;
            out[gi] = fmaxf(st[srow + co2], 0.f);
        }
    }
}

// ---------------- launch ----------------
extern "C" void kernel_launch(void* const* d_in, const int* in_sizes, int n_in,
                              void* d_out, int out_size) {
    (void)in_sizes; (void)n_in; (void)out_size;
    const float* x  = (const float*)d_in[0];
    const float* w1 = (const float*)d_in[1];
    const float* g1 = (const float*)d_in[2];
    const float* b1 = (const float*)d_in[3];
    const float* m1 = (const float*)d_in[4];
    const float* v1 = (const float*)d_in[5];
    const float* w2 = (const float*)d_in[6];
    const float* g2 = (const float*)d_in[7];
    const float* b2 = (const float*)d_in[8];
    const float* m2 = (const float*)d_in[9];
    const float* v2 = (const float*)d_in[10];
    float* out = (float*)d_out;

    cudaFuncSetAttribute(gemm_wino<0>, cudaFuncAttributeMaxDynamicSharedMemorySize, G_SMEM);
    cudaFuncSetAttribute(gemm_wino<1>, cudaFuncAttributeMaxDynamicSharedMemorySize, G_SMEM);

    prep<<<dim3(257, 2), 256>>>(w1, w2, g1, b1, m1, v1, g2, b2, m2, v2);
    xpose<<<dim3(25, 8, 64), dim3(32, 8)>>>(x);

    // conv1
    wino_in<0><<<1568, 256>>>();
    gemm_wino<0><<<dim3(2, 98, 16), 256, G_SMEM>>>();
    wino_out<0><<<3136, 256>>>(nullptr);

    // conv2
    wino_in<1><<<1568, 256>>>();
    gemm_wino<1><<<dim3(2, 98, 16), 256, G_SMEM>>>();
    wino_out<1><<<3136, 256>>>(out);
}

// round 17
// speedup vs baseline: 1.1226x; 1.0151x over previous
#include <cuda_runtime.h>
#include <cuda_fp16.h>
#include <cstdint>

// ---------------- constants ----------------
#define C     256
#define NB    64
#define HW    784
#define NPAD  900                 // 30*30 padded image
#define PADROWS (NB*NPAD)         // 57600
#define NTT   12544               // total 2x2 tiles = 64*14*14
#define VSTRIDE ((size_t)NTT*C)   // 3211264

// gemm tiling
#define GSTAGES 3
#define G_ABYTES 16384            // 128 rows x 64 fp16
#define G_BBYTES 16384
#define G_STG (G_ABYTES + G_BBYTES)        // 32 KB
#define G_SMEM (GSTAGES * G_STG)           // 96 KB -> 2 CTAs/SM

// ---------------- device scratch (only touched from device code!) ----------------
__device__ __half g_xh[PADROWS*C];   // padded NHWC input fp16 (halo stays 0)
__device__ __half g_o1[PADROWS*C];   // padded conv1 output fp16 (halo stays 0)
__device__ __half g_U1[16*C*C];      // transformed weights GgG^T
__device__ __half g_U2[16*C*C];
__device__ __half g_V[16*NTT*C];     // input transform (fp16)
__device__ __half g_Mh[16*NTT*C];    // gemm output (fp16)
__device__ float g_s1[C], g_b1[C], g_s2[C], g_b2[C];

// ---------------- ptx helpers ----------------
__device__ __forceinline__ uint32_t smem_u32(const void* p) {
    uint32_t a;
    asm("{ .reg .u64 t; cvta.to.shared.u64 t, %1; cvt.u32.u64 %0, t; }" : "=r"(a) : "l"(p));
    return a;
}
__device__ __forceinline__ void cp16(uint32_t dst, const void* src) {
    asm volatile("cp.async.cg.shared.global [%0], [%1], 16;\n" :: "r"(dst), "l"(src));
}
__device__ __forceinline__ void cp_commit() { asm volatile("cp.async.commit_group;\n" ::); }
__device__ __forceinline__ void cp_wait1()  { asm volatile("cp.async.wait_group 1;\n" ::: "memory"); }
__device__ __forceinline__ void ldmx4(uint32_t* r, uint32_t addr) {
    asm volatile("ldmatrix.sync.aligned.m8n8.x4.shared.b16 {%0,%1,%2,%3}, [%4];"
        : "=r"(r[0]), "=r"(r[1]), "=r"(r[2]), "=r"(r[3]) : "r"(addr));
}
__device__ __forceinline__ void mma16816_f(float* c, const uint32_t* a, const uint32_t* b) {
    asm volatile("mma.sync.aligned.m16n8k16.row.col.f32.f16.f16.f32 "
        "{%0,%1,%2,%3}, {%4,%5,%6,%7}, {%8,%9}, {%0,%1,%2,%3};"
        : "+f"(c[0]), "+f"(c[1]), "+f"(c[2]), "+f"(c[3])
        : "r"(a[0]), "r"(a[1]), "r"(a[2]), "r"(a[3]), "r"(b[0]), "r"(b[1]));
}
#define SW(off) ((off) ^ (((off) >> 3) & 0x70))

// ---------------- prep: BN consts + weight transform U = G g G^T ----------------
__global__ void prep(const float* __restrict__ w1, const float* __restrict__ w2,
                     const float* __restrict__ g1, const float* __restrict__ b1,
                     const float* __restrict__ m1, const float* __restrict__ v1,
                     const float* __restrict__ g2, const float* __restrict__ b2,
                     const float* __restrict__ m2, const float* __restrict__ v2) {
    int co = blockIdx.x, which = blockIdx.y, ci = threadIdx.x;
    if (co == 256) {
        if (which == 0) {
            float inv = g1[ci] * rsqrtf(v1[ci] + 1e-5f);
            g_s1[ci] = 0.02f * inv; g_b1[ci] = b1[ci] - m1[ci] * inv;
        } else {
            float inv = g2[ci] * rsqrtf(v2[ci] + 1e-5f);
            g_s2[ci] = 0.02f * inv; g_b2[ci] = b2[ci] - m2[ci] * inv;
        }
        return;
    }
    const float* w = which ? w2 : w1;
    __half* U = which ? g_U2 : g_U1;
    float g[3][3];
    #pragma unroll
    for (int r = 0; r < 3; r++)
        #pragma unroll
        for (int c = 0; c < 3; c++) {
            float v = w[((co * C + ci) * 3 + r) * 3 + c];
            g[r][c] = (v > 0.f) ? 1.f : ((v < 0.f) ? -1.f : 0.f);
        }
    float T[4][3];
    #pragma unroll
    for (int c = 0; c < 3; c++) {
        T[0][c] = g[0][c];
        T[1][c] = 0.5f * (g[0][c] + g[1][c] + g[2][c]);
        T[2][c] = 0.5f * (g[0][c] - g[1][c] + g[2][c]);
        T[3][c] = g[2][c];
    }
    #pragma unroll
    for (int i = 0; i < 4; i++) {
        float u0 = T[i][0];
        float u1 = 0.5f * (T[i][0] + T[i][1] + T[i][2]);
        float u2 = 0.5f * (T[i][0] - T[i][1] + T[i][2]);
        float u3 = T[i][2];
        int base = co * C + ci;
        U[(i * 4 + 0) * (C * C) + base] = __float2half_rn(u0);
        U[(i * 4 + 1) * (C * C) + base] = __float2half_rn(u1);
        U[(i * 4 + 2) * (C * C) + base] = __float2half_rn(u2);
        U[(i * 4 + 3) * (C * C) + base] = __float2half_rn(u3);
    }
}

// ---------------- NCHW -> padded NHWC fp16 (vectorized) ----------------
// block 256; grid (25 hwt, 8 ct, 64 n). float4 loads, uint2 (4x fp16) stores.
__global__ __launch_bounds__(256) void xpose(const float* __restrict__ x) {
    __shared__ float t[32][33];
    const int n = blockIdx.z, hwt = blockIdx.x, ct = blockIdx.y;
    const int tid = threadIdx.x;

    // load: (8 hw-quads, 32 c) -> smem stage
    {
        const int tx = tid & 7, ty = tid >> 3;
        const int hw4 = hwt * 32 + tx * 4;
        const int c = ct * 32 + ty;
        if (hw4 < HW) {
            float4 v = *(const float4*)&x[((size_t)n * C + c) * HW + hw4];
            t[ty][tx * 4 + 0] = v.x;
            t[ty][tx * 4 + 1] = v.y;
            t[ty][tx * 4 + 2] = v.z;
            t[ty][tx * 4 + 3] = v.w;
        } else {
            t[ty][tx * 4 + 0] = 0.f; t[ty][tx * 4 + 1] = 0.f;
            t[ty][tx * 4 + 2] = 0.f; t[ty][tx * 4 + 3] = 0.f;
        }
    }
    __syncthreads();

    // store: (8 c-quads, 32 hw) -> g_xh, 4 halves (uint2) per thread
    {
        const int cq = tid & 7;          // c quad within 32-c group
        const int hwl = tid >> 3;        // 0..31
        const int hw = hwt * 32 + hwl;
        if (hw < HW) {
            const int h = hw / 28, w = hw - h * 28;
            __half2 lo = __floats2half2_rn(t[cq * 4 + 0][hwl], t[cq * 4 + 1][hwl]);
            __half2 hi = __floats2half2_rn(t[cq * 4 + 2][hwl], t[cq * 4 + 3][hwl]);
            uint2 pk = make_uint2(*(uint32_t*)&lo, *(uint32_t*)&hi);
            *(uint2*)&g_xh[((size_t)(n * NPAD + (h + 1) * 30 + w + 1)) * C + ct * 32 + cq * 4] = pk;
        }
    }
}

// ---------------- input transform: V = B^T d B ----------------
// block 256 = 8 tile-slots x 32 ci-octets; grid 1568
template <int WHICH>
__global__ __launch_bounds__(256) void wino_in() {
    const __half* src = WHICH ? g_o1 : g_xh;
    int t = threadIdx.x;
    int cig = t & 31, slot = t >> 5;
    int mp = blockIdx.x * 8 + slot;
    int n = mp / 196; int r0 = mp - n * 196;
    int ti = r0 / 14, tj = r0 - ti * 14;
    const __half* base = src + ((size_t)(n * NPAD + 2 * ti * 30 + 2 * tj)) * C + cig * 8;

    uint4 d16[16];
    #pragma unroll
    for (int i = 0; i < 4; i++)
        #pragma unroll
        for (int j = 0; j < 4; j++)
            d16[i * 4 + j] = *(const uint4*)(base + (size_t)(i * 30 + j) * C);

    __half2 vout[16][4];
    #pragma unroll
    for (int k = 0; k < 8; k++) {
        float d[4][4];
        #pragma unroll
        for (int p = 0; p < 16; p++) {
            uint32_t wd = ((const uint32_t*)&d16[p])[k >> 1];
            float2 f = __half22float2(*(__half2*)&wd);
            d[p >> 2][p & 3] = (k & 1) ? f.y : f.x;
        }
        float tt[4][4];
        #pragma unroll
        for (int c = 0; c < 4; c++) {
            tt[0][c] = d[0][c] - d[2][c];
            tt[1][c] = d[1][c] + d[2][c];
            tt[2][c] = d[2][c] - d[1][c];
            tt[3][c] = d[1][c] - d[3][c];
        }
        #pragma unroll
        for (int i = 0; i < 4; i++) {
            float v[4];
            v[0] = tt[i][0] - tt[i][2];
            v[1] = tt[i][1] + tt[i][2];
            v[2] = tt[i][2] - tt[i][1];
            v[3] = tt[i][1] - tt[i][3];
            #pragma unroll
            for (int j = 0; j < 4; j++) {
                __half hv = __float2half_rn(v[j]);
                int nu = i * 4 + j, wdi = k >> 1;
                if ((k & 1) == 0) vout[nu][wdi] = __halves2half2(hv, hv);
                else vout[nu][wdi] = __halves2half2(__low2half(vout[nu][wdi]), hv);
            }
        }
    }
    size_t mo = (size_t)mp * C + cig * 8;
    #pragma unroll
    for (int nu = 0; nu < 16; nu++)
        *(uint4*)(g_V + nu * VSTRIDE + mo) = *(uint4*)vout[nu];
}

// ---------------- batched GEMM: M[nu] = V[nu] * U[nu]^T ----------------
// grid (2, 98, 16), block 256 (8 warps 2x4, warp tile 64x32), 3-stage 96KB, occ 2.
// f32 accumulation (legacy-HMMA chip floor); A fragments double-buffered across ks.
template <int WHICH>
__global__ __launch_bounds__(256, 2) void gemm_wino() {
    extern __shared__ char smem[];
    const uint32_t sb = smem_u32(smem);
    const int bn_ = blockIdx.x, bm = blockIdx.y, nu = blockIdx.z;
    const __half* Vb = g_V + (size_t)nu * VSTRIDE;
    const __half* Ub = (WHICH ? g_U2 : g_U1) + (size_t)nu * (C * C);

    const int tid = threadIdx.x;
    const int wid = tid >> 5, lane = tid & 31;
    const int row = tid >> 1, hf = tid & 1;
    const __half* Arow = Vb + (size_t)(bm * 128 + row) * C + hf * 32;
    const __half* Brow = Ub + (size_t)(bn_ * 128 + row) * C + hf * 32;

    auto loadChunk = [&](int k) {
        const uint32_t base = sb + (k % GSTAGES) * G_STG;
        const uint32_t ro = (uint32_t)row * 128 + hf * 64;
        #pragma unroll
        for (int i = 0; i < 4; i++) {
            uint32_t o = ro + i * 16;
            cp16(base + SW(o), Arow + k * 64 + i * 8);
            cp16(base + G_ABYTES + SW(o), Brow + k * 64 + i * 8);
        }
        cp_commit();
    };

    const int wm = wid & 1, wn = wid >> 1;
    const int lq = lane >> 3, l7 = lane & 7;
    const int aro = (lq & 1) * 8 + l7, aqh = lq >> 1;
    const int bro = (lq >> 1) * 8 + l7, bqh = lq & 1;

    float acc[4][4][4];
    #pragma unroll
    for (int i = 0; i < 4; i++)
        #pragma unroll
        for (int j = 0; j < 4; j++)
            #pragma unroll
            for (int k = 0; k < 4; k++) acc[i][j][k] = 0.f;

    uint32_t af[2][4][4];

    loadChunk(0);
    loadChunk(1);

    #pragma unroll
    for (int k = 0; k < 4; k++) {
        cp_wait1();
        __syncthreads();
        if (k + 2 < 4) loadChunk(k + 2); else cp_commit();

        const uint32_t aB = sb + (k % GSTAGES) * G_STG + (uint32_t)(wm * 64) * 128;
        const uint32_t bB = sb + (k % GSTAGES) * G_STG + G_ABYTES + (uint32_t)(wn * 32) * 128;

        #pragma unroll
        for (int mt = 0; mt < 4; mt++) {
            int rw = mt * 16 + aro;
            ldmx4(af[0][mt], aB + (uint32_t)rw * 128 + (uint32_t)((aqh ^ (rw & 7)) * 16));
        }

        #pragma unroll
        for (int ks = 0; ks < 4; ks++) {
            const int cur = ks & 1, nxt = cur ^ 1;
            if (ks < 3) {
                #pragma unroll
                for (int mt = 0; mt < 4; mt++) {
                    int rw = mt * 16 + aro;
                    ldmx4(af[nxt][mt],
                          aB + (uint32_t)rw * 128 + (uint32_t)((((ks + 1) * 2 + aqh) ^ (rw & 7)) * 16));
                }
            }
            uint32_t bf[2][4];
            #pragma unroll
            for (int nt2 = 0; nt2 < 2; nt2++) {
                int rw = nt2 * 16 + bro;
                uint32_t cx = (uint32_t)(((ks * 2 + bqh) ^ (rw & 7)) * 16);
                ldmx4(bf[nt2], bB + (uint32_t)rw * 128 + cx);
            }
            #pragma unroll
            for (int mt = 0; mt < 4; mt++)
                #pragma unroll
                for (int nt = 0; nt < 4; nt++)
                    mma16816_f(acc[mt][nt], af[cur][mt], &bf[nt >> 1][(nt & 1) * 2]);
        }
    }

    // epilogue: fp16 M
    const int lr = lane >> 2, lc = (lane & 3) * 2;
    __half* Mb = g_Mh + (size_t)nu * VSTRIDE;
    #pragma unroll
    for (int nt = 0; nt < 4; nt++) {
        const int co = bn_ * 128 + wn * 32 + nt * 8 + lc;
        #pragma unroll
        for (int mt = 0; mt < 4; mt++) {
            const int m0 = bm * 128 + wm * 64 + mt * 16 + lr;
            *(__half2*)(Mb + (size_t)m0 * C + co) = __floats2half2_rn(acc[mt][nt][0], acc[mt][nt][1]);
            *(__half2*)(Mb + (size_t)(m0 + 8) * C + co) = __floats2half2_rn(acc[mt][nt][2], acc[mt][nt][3]);
        }
    }
}

// ---------------- output transform: Y = A^T M A, + BN (+res) + ReLU ----------------
// block 256 = 4 tile-slots x 64 co-quads; grid 3136
// MODE 1: residual comes from g_xh (fp16 NHWC padded)
template <int MODE>
__global__ __launch_bounds__(256) void wino_out(float* __restrict__ out) {
    __shared__ float st[16 * 257];   // MODE1 transpose buffer
    int t = threadIdx.x;
    int cog = t & 63, slot = t >> 6;
    int mp = blockIdx.x * 4 + slot;
    int n = mp / 196; int r0 = mp - n * 196;
    int ti = r0 / 14, tj = r0 - ti * 14;
    const float* scp = MODE ? g_s2 : g_s1;
    const float* bip = MODE ? g_b2 : g_b1;

    size_t mo = (size_t)mp * C + cog * 4;
    uint2 m16[16];
    #pragma unroll
    for (int nu = 0; nu < 16; nu++)
        m16[nu] = *(const uint2*)(g_Mh + nu * VSTRIDE + mo);

    uint2 rx[4];
    if (MODE == 1) {
        const __half* xh = g_xh + ((size_t)(n * NPAD + (2 * ti + 1) * 30 + 2 * tj + 1)) * C + cog * 4;
        rx[0] = *(const uint2*)(xh);
        rx[1] = *(const uint2*)(xh + C);
        rx[2] = *(const uint2*)(xh + 30 * C);
        rx[3] = *(const uint2*)(xh + 31 * C);
    }

    __half2 oreg[4][2];
    #pragma unroll
    for (int k = 0; k < 4; k++) {
        float Mv[16];
        #pragma unroll
        for (int p = 0; p < 16; p++) {
            uint32_t wd = ((const uint32_t*)&m16[p])[k >> 1];
            float2 f = __half22float2(*(__half2*)&wd);
            Mv[p] = (k & 1) ? f.y : f.x;
        }
        float t0[4], t1[4];
        #pragma unroll
        for (int c = 0; c < 4; c++) {
            t0[c] = Mv[c] + Mv[4 + c] + Mv[8 + c];
            t1[c] = Mv[4 + c] - Mv[8 + c] - Mv[12 + c];
        }
        float y[4];
        y[0] = t0[0] + t0[1] + t0[2];
        y[1] = t0[1] - t0[2] - t0[3];
        y[2] = t1[0] + t1[1] + t1[2];
        y[3] = t1[1] - t1[2] - t1[3];
        const int co = cog * 4 + k;
        const float s = scp[co], bb = bip[co];
        #pragma unroll
        for (int p = 0; p < 4; p++) y[p] = y[p] * s + bb;

        if (MODE == 0) {
            #pragma unroll
            for (int p = 0; p < 4; p++) {
                __half hv = __float2half_rn(fmaxf(y[p], 0.f));
                int wdi = k >> 1;
                if ((k & 1) == 0) oreg[p][wdi] = __halves2half2(hv, hv);
                else oreg[p][wdi] = __halves2half2(__low2half(oreg[p][wdi]), hv);
            }
        } else {
            #pragma unroll
            for (int p = 0; p < 4; p++) {
                float r = __half2float(((const __half*)&rx[p])[k]);
                st[(slot * 4 + p) * 257 + co] = y[p] + r;
            }
        }
    }

    if (MODE == 0) {
        __half* dst = g_o1 + ((size_t)(n * NPAD + (2 * ti + 1) * 30 + 2 * tj + 1)) * C + cog * 4;
        *(uint2*)(dst)          = *(uint2*)oreg[0];
        *(uint2*)(dst + C)      = *(uint2*)oreg[1];
        *(uint2*)(dst + 30 * C) = *(uint2*)oreg[2];
        *(uint2*)(dst + 31 * C) = *(uint2*)oreg[3];
    } else {
        __syncthreads();
        const int l = t & 7, q = t >> 3;
        const int s2 = l >> 1, c2 = l & 1;
        const int r2 = q & 1, coq = q >> 1;          // coq 0..15
        const int mp2 = blockIdx.x * 4 + s2;
        const int n2 = mp2 / 196; int rr2 = mp2 - n2 * 196;
        const int ti2 = rr2 / 14, tj2 = rr2 - ti2 * 14;
        const int h = 2 * ti2 + r2, w = 2 * tj2 + c2;
        const int srow = (s2 * 4 + r2 * 2 + c2) * 257;
        #pragma unroll
        for (int cc = 0; cc < 16; cc++) {
            const int co2 = coq * 16 + cc;
            const size_t gi = ((size_t)n2 * C + co2) * HW + h * 28 + w;
            out[gi] = fmaxf(st[srow + co2], 0.f);
        }
    }
}

// ---------------- launch ----------------
extern "C" void kernel_launch(void* const* d_in, const int* in_sizes, int n_in,
                              void* d_out, int out_size) {
    (void)in_sizes; (void)n_in; (void)out_size;
    const float* x  = (const float*)d_in[0];
    const float* w1 = (const float*)d_in[1];
    const float* g1 = (const float*)d_in[2];
    const float* b1 = (const float*)d_in[3];
    const float* m1 = (const float*)d_in[4];
    const float* v1 = (const float*)d_in[5];
    const float* w2 = (const float*)d_in[6];
    const float* g2 = (const float*)d_in[7];
    const float* b2 = (const float*)d_in[8];
    const float* m2 = (const float*)d_in[9];
    const float* v2 = (const float*)d_in[10];
    float* out = (float*)d_out;

    cudaFuncSetAttribute(gemm_wino<0>, cudaFuncAttributeMaxDynamicSharedMemorySize, G_SMEM);
    cudaFuncSetAttribute(gemm_wino<1>, cudaFuncAttributeMaxDynamicSharedMemorySize, G_SMEM);

    prep<<<dim3(257, 2), 256>>>(w1, w2, g1, b1, m1, v1, g2, b2, m2, v2);
    xpose<<<dim3(25, 8, 64), 256>>>(x);

    // conv1
    wino_in<0><<<1568, 256>>>();
    gemm_wino<0><<<dim3(2, 98, 16), 256, G_SMEM>>>();
    wino_out<0><<<3136, 256>>>(nullptr);

    // conv2
    wino_in<1><<<1568, 256>>>();
    gemm_wino<1><<<dim3(2, 98, 16), 256, G_SMEM>>>();
    wino_out<1><<<3136, 256>>>(out);
}